// round 4
// baseline (speedup 1.0000x reference)
#include <cuda_runtime.h>
#include <cuda_bf16.h>
#include <cstdint>
#include <math.h>

// KMeansClusteringLoss via warp-level bf16 HMMA (mma.sync m16n8k16).
//   cost(l,c) = |mu_c|^2 - 2 <z_l, mu_c>,  d(l) = sqrt(max(|z_l|^2 + min_c cost, 0))
//   out = mean_l d(l)
//
// R4: 16 warps (512 thr), warps split 512 centroids into 2 halves of 256;
// 4 independent accumulator chains per n-iteration; dynamic tile stealing.

#define KDIM  128
#define CDIM  512
#define MT    128          // z rows per tile
#define NTHREADS 512       // 16 warps
#define NHALF 256          // centroids per warp-half

#define STRIDE_B 272       // 128 bf16 (256B) + 16B pad -> conflict-free LDSM

// dynamic smem layout (bytes)
#define SM_MU   0                                   // 512 x 272 = 139264
#define SM_Z    (SM_MU + CDIM * STRIDE_B)           // 128 x 272 = 34816
#define SM_M2   (SM_Z + MT * STRIDE_B)              // 512 f32
#define SM_Z2   (SM_M2 + CDIM * 4)                  // 128 f32
#define SM_MH   (SM_Z2 + MT * 4)                    // 128 x 2 f32 (min per half)
#define SM_RED  (SM_MH + MT * 2 * 4)                // 4 f32
#define SM_TILE (SM_RED + 16)                       // 1 int
#define SMEM_BYTES (SM_TILE + 16)

__device__ float g_sum;
__device__ unsigned int g_cnt;
__device__ unsigned int g_tile;
__device__ __align__(16) __nv_bfloat16 g_mu_bf[CDIM * KDIM];
__device__ float g_m2[CDIM];

// ---------------- helpers ----------------
__device__ __forceinline__ uint32_t smem_u32(const void* p) {
    uint32_t a;
    asm("{ .reg .u64 t; cvta.to.shared.u64 t, %1; cvt.u32.u64 %0, t; }" : "=r"(a) : "l"(p));
    return a;
}
__device__ __forceinline__ void ldsm_x4(uint32_t& r0, uint32_t& r1, uint32_t& r2, uint32_t& r3,
                                        uint32_t addr) {
    asm volatile("ldmatrix.sync.aligned.m8n8.x4.shared.b16 {%0,%1,%2,%3}, [%4];"
                 : "=r"(r0), "=r"(r1), "=r"(r2), "=r"(r3) : "r"(addr));
}
__device__ __forceinline__ void ldsm_x2(uint32_t& r0, uint32_t& r1, uint32_t addr) {
    asm volatile("ldmatrix.sync.aligned.m8n8.x2.shared.b16 {%0,%1}, [%2];"
                 : "=r"(r0), "=r"(r1) : "r"(addr));
}
__device__ __forceinline__ void mma_bf16(float* d, const uint32_t* a, const uint32_t* b) {
    asm volatile(
        "mma.sync.aligned.m16n8k16.row.col.f32.bf16.bf16.f32 "
        "{%0,%1,%2,%3}, {%4,%5,%6,%7}, {%8,%9}, {%0,%1,%2,%3};"
        : "+f"(d[0]), "+f"(d[1]), "+f"(d[2]), "+f"(d[3])
        : "r"(a[0]), "r"(a[1]), "r"(a[2]), "r"(a[3]), "r"(b[0]), "r"(b[1]));
}

// ---------------- prologue: mu fp32 -> bf16, m2, zero accumulators ----------------
__global__ void km_prep(const float* __restrict__ mu) {
    if (blockIdx.x == 0 && threadIdx.x == 0) { g_sum = 0.0f; g_cnt = 0u; g_tile = 0u; }
    int warp = (blockIdx.x * blockDim.x + threadIdx.x) >> 5;   // 1 warp per centroid
    int lane = threadIdx.x & 31;
    if (warp >= CDIM) return;

    float4 v = reinterpret_cast<const float4*>(mu + warp * KDIM)[lane];
    __nv_bfloat162 p0 = __floats2bfloat162_rn(v.x, v.y);
    __nv_bfloat162 p1 = __floats2bfloat162_rn(v.z, v.w);
    reinterpret_cast<__nv_bfloat162*>(g_mu_bf + warp * KDIM)[lane * 2 + 0] = p0;
    reinterpret_cast<__nv_bfloat162*>(g_mu_bf + warp * KDIM)[lane * 2 + 1] = p1;

    float a0 = __bfloat162float(p0.x), a1 = __bfloat162float(p0.y);
    float a2 = __bfloat162float(p1.x), a3 = __bfloat162float(p1.y);
    float s = a0 * a0 + a1 * a1 + a2 * a2 + a3 * a3;
    #pragma unroll
    for (int o = 16; o > 0; o >>= 1) s += __shfl_down_sync(0xffffffffu, s, o);
    if (lane == 0) g_m2[warp] = s;
}

// ---------------- persistent main kernel ----------------
__global__ void __launch_bounds__(NTHREADS, 1) km_main(
    const float* __restrict__ z, float* __restrict__ out, int L, int ntiles)
{
    extern __shared__ char smem[];
    const uint32_t sbase = smem_u32(smem);
    float* m2s = reinterpret_cast<float*>(smem + SM_M2);
    float* z2s = reinterpret_cast<float*>(smem + SM_Z2);
    float* mh  = reinterpret_cast<float*>(smem + SM_MH);    // [row][half]
    float* red = reinterpret_cast<float*>(smem + SM_RED);
    volatile int* s_tile = reinterpret_cast<volatile int*>(smem + SM_TILE);

    const int tid  = threadIdx.x;
    const int wid  = tid >> 5;
    const int lane = tid & 31;
    const int tg   = lane & 3;          // col pair within n8
    const int g    = lane >> 2;         // row within m16 half
    const int rw   = wid & 7;           // row-group index
    const int nh   = wid >> 3;          // centroid half (0/1)
    const int r0   = rw * 16;
    const int nbase = nh * NHALF;

    // ---- resident mu tile: 512 x 128 bf16 into padded SMEM rows ----
    for (int idx = tid; idx < CDIM * 16; idx += NTHREADS) {      // 16B chunks
        int c = idx >> 4, kc = idx & 15;
        uint4 q = reinterpret_cast<const uint4*>(g_mu_bf)[idx];
        *reinterpret_cast<uint4*>(smem + SM_MU + c * STRIDE_B + kc * 16) = q;
    }
    for (int i = tid; i < CDIM; i += NTHREADS) m2s[i] = g_m2[i];

    const uint32_t bb = sbase + SM_MU + (lane & 7) * STRIDE_B + ((lane & 8) ? 16 : 0);

    while (true) {
        if (tid == 0) *s_tile = (int)atomicAdd(&g_tile, 1u);
        __syncthreads();
        const int tile = *s_tile;
        if (tile >= ntiles) break;
        const size_t m0 = (size_t)tile * MT;

        // ---- load z tile fp32 -> bf16 into padded SMEM ----
        for (int idx = tid; idx < MT * 16; idx += NTHREADS) {
            int row = idx >> 4, kc = idx & 15;
            const float4* p = reinterpret_cast<const float4*>(z + (m0 + row) * KDIM + kc * 8);
            float4 v0 = p[0], v1 = p[1];
            __nv_bfloat162 b0 = __floats2bfloat162_rn(v0.x, v0.y);
            __nv_bfloat162 b1 = __floats2bfloat162_rn(v0.z, v0.w);
            __nv_bfloat162 b2 = __floats2bfloat162_rn(v1.x, v1.y);
            __nv_bfloat162 b3 = __floats2bfloat162_rn(v1.z, v1.w);
            uint4 q;
            q.x = *reinterpret_cast<uint32_t*>(&b0);
            q.y = *reinterpret_cast<uint32_t*>(&b1);
            q.z = *reinterpret_cast<uint32_t*>(&b2);
            q.w = *reinterpret_cast<uint32_t*>(&b3);
            *reinterpret_cast<uint4*>(smem + SM_Z + row * STRIDE_B + kc * 16) = q;
        }
        __syncthreads();

        // ---- |z|^2 per row from the same bf16 values ----
        if (tid < MT) {
            float s = 0.0f;
            #pragma unroll
            for (int j = 0; j < 16; j++) {
                uint4 q = *reinterpret_cast<const uint4*>(smem + SM_Z + tid * STRIDE_B + j * 16);
                uint32_t u[4] = {q.x, q.y, q.z, q.w};
                #pragma unroll
                for (int e = 0; e < 4; e++) {
                    float lo = __uint_as_float(u[e] << 16);
                    float hi = __uint_as_float(u[e] & 0xffff0000u);
                    s = fmaf(lo, lo, s);
                    s = fmaf(hi, hi, s);
                }
            }
            z2s[tid] = s;
        }

        // ---- A fragments: 8 k-steps of m16k16 ----
        uint32_t A[8][4];
        {
            uint32_t abase = sbase + SM_Z + (r0 + (lane & 15)) * STRIDE_B + ((lane & 16) ? 16 : 0);
            #pragma unroll
            for (int kk = 0; kk < 8; kk++)
                ldsm_x4(A[kk][0], A[kk][1], A[kk][2], A[kk][3], abase + kk * 32);
        }

        // ---- 256 centroids per warp: 8 iters x (4 n8-tiles, 4 indep chains) ----
        float mn0 = INFINITY, mn1 = INFINITY;
        #pragma unroll 1
        for (int nt = 0; nt < NHALF / 32; nt++) {
            const int n0 = nbase + nt * 32;
            float acc[4][4] = {};
            const uint32_t ba = bb + n0 * STRIDE_B;
            #pragma unroll
            for (int kk = 0; kk < 8; kk++) {
                uint32_t b[4][2];
                #pragma unroll
                for (int c = 0; c < 4; c++)
                    ldsm_x2(b[c][0], b[c][1], ba + c * 8 * STRIDE_B + kk * 32);
                #pragma unroll
                for (int c = 0; c < 4; c++)
                    mma_bf16(acc[c], A[kk], b[c]);
            }
            #pragma unroll
            for (int c = 0; c < 4; c++) {
                float2 m = *reinterpret_cast<const float2*>(&m2s[n0 + 8 * c + 2 * tg]);
                mn0 = fminf(mn0, fmaf(-2.0f, acc[c][0], m.x));
                mn0 = fminf(mn0, fmaf(-2.0f, acc[c][1], m.y));
                mn1 = fminf(mn1, fmaf(-2.0f, acc[c][2], m.x));
                mn1 = fminf(mn1, fmaf(-2.0f, acc[c][3], m.y));
            }
        }

        // ---- min across the 4 threads sharing each row ----
        mn0 = fminf(mn0, __shfl_xor_sync(0xffffffffu, mn0, 1));
        mn0 = fminf(mn0, __shfl_xor_sync(0xffffffffu, mn0, 2));
        mn1 = fminf(mn1, __shfl_xor_sync(0xffffffffu, mn1, 1));
        mn1 = fminf(mn1, __shfl_xor_sync(0xffffffffu, mn1, 2));

        if (tg == 0) {
            mh[(r0 + g) * 2 + nh]     = mn0;
            mh[(r0 + 8 + g) * 2 + nh] = mn1;
        }
        __syncthreads();

        // ---- combine halves, sqrt, block sum ----
        float s = 0.0f;
        if (tid < MT) {
            float mn = fminf(mh[tid * 2 + 0], mh[tid * 2 + 1]);
            s = sqrtf(fmaxf(z2s[tid] + mn, 0.0f));
        }
        #pragma unroll
        for (int o = 16; o > 0; o >>= 1) s += __shfl_down_sync(0xffffffffu, s, o);
        if (tid < MT && lane == 0) red[wid] = s;
        __syncthreads();

        if (tid == 0) {
            float t = red[0] + red[1] + red[2] + red[3];
            atomicAdd(&g_sum, t);
            __threadfence();
            unsigned int c = atomicAdd(&g_cnt, 1u);
            if (c == (unsigned int)(ntiles - 1)) {
                out[0] = (*(volatile float*)&g_sum) / (float)L;
            }
        }
        __syncthreads();   // smem safe to reuse
    }
}

extern "C" void kernel_launch(void* const* d_in, const int* in_sizes, int n_in,
                              void* d_out, int out_size) {
    const float* z  = (const float*)d_in[0];
    const float* mu = (const float*)d_in[1];
    float* out = (float*)d_out;

    int L = in_sizes[0] / KDIM;   // 65536
    int ntiles = L / MT;          // 512

    static int nsm = 0;
    if (nsm == 0) {
        cudaDeviceGetAttribute(&nsm, cudaDevAttrMultiProcessorCount, 0);
        cudaFuncSetAttribute(km_main, cudaFuncAttributeMaxDynamicSharedMemorySize, SMEM_BYTES);
    }
    int grid = (ntiles < nsm) ? ntiles : nsm;

    km_prep<<<64, 256>>>(mu);
    km_main<<<grid, NTHREADS, SMEM_BYTES>>>(z, out, L, ntiles);
}

// round 5
// speedup vs baseline: 1.0284x; 1.0284x over previous
#include <cuda_runtime.h>
#include <cuda_bf16.h>
#include <cstdint>
#include <math.h>

// KMeansClusteringLoss via warp-level bf16 HMMA (mma.sync m16n8k16).
//   cost(l,c) = |mu_c|^2 - 2 <z_l, mu_c>,  d(l) = sqrt(max(|z_l|^2 + min_c cost, 0))
//   out = mean_l d(l)
//
// R5: m32 per warp (A fully register-resident, 64 regs) x 128 centroids;
// ldsm_x4 B loads (1 LDSM per 4 HMMAs) -> smem crossbar traffic halved vs R4.

#define KDIM  128
#define CDIM  512
#define MT    128          // z rows per tile
#define NTHREADS 512       // 16 warps = 4 row-groups (m32) x 4 centroid quarters
#define NQ    128          // centroids per warp

#define STRIDE_B 272       // 128 bf16 (256B) + 16B pad -> conflict-free LDSM

// dynamic smem layout (bytes)
#define SM_MU   0                                   // 512 x 272 = 139264
#define SM_Z    (SM_MU + CDIM * STRIDE_B)           // 128 x 272 = 34816
#define SM_M2   (SM_Z + MT * STRIDE_B)              // 512 f32
#define SM_Z2   (SM_M2 + CDIM * 4)                  // 128 f32
#define SM_MH   (SM_Z2 + MT * 4)                    // 128 x 4 f32 (min per quarter)
#define SM_RED  (SM_MH + MT * 4 * 4)                // 4 f32
#define SM_TILE (SM_RED + 16)                       // 1 int
#define SMEM_BYTES (SM_TILE + 16)

__device__ float g_sum;
__device__ unsigned int g_cnt;
__device__ unsigned int g_tile;
__device__ __align__(16) __nv_bfloat16 g_mu_bf[CDIM * KDIM];
__device__ float g_m2[CDIM];

// ---------------- helpers ----------------
__device__ __forceinline__ uint32_t smem_u32(const void* p) {
    uint32_t a;
    asm("{ .reg .u64 t; cvta.to.shared.u64 t, %1; cvt.u32.u64 %0, t; }" : "=r"(a) : "l"(p));
    return a;
}
__device__ __forceinline__ void ldsm_x4(uint32_t& r0, uint32_t& r1, uint32_t& r2, uint32_t& r3,
                                        uint32_t addr) {
    asm volatile("ldmatrix.sync.aligned.m8n8.x4.shared.b16 {%0,%1,%2,%3}, [%4];"
                 : "=r"(r0), "=r"(r1), "=r"(r2), "=r"(r3) : "r"(addr));
}
__device__ __forceinline__ void mma_bf16(float* d, const uint32_t* a,
                                         uint32_t b0, uint32_t b1) {
    asm volatile(
        "mma.sync.aligned.m16n8k16.row.col.f32.bf16.bf16.f32 "
        "{%0,%1,%2,%3}, {%4,%5,%6,%7}, {%8,%9}, {%0,%1,%2,%3};"
        : "+f"(d[0]), "+f"(d[1]), "+f"(d[2]), "+f"(d[3])
        : "r"(a[0]), "r"(a[1]), "r"(a[2]), "r"(a[3]), "r"(b0), "r"(b1));
}

// ---------------- prologue: mu fp32 -> bf16, m2, zero accumulators ----------------
__global__ void km_prep(const float* __restrict__ mu) {
    if (blockIdx.x == 0 && threadIdx.x == 0) { g_sum = 0.0f; g_cnt = 0u; g_tile = 0u; }
    int warp = (blockIdx.x * blockDim.x + threadIdx.x) >> 5;   // 1 warp per centroid
    int lane = threadIdx.x & 31;
    if (warp >= CDIM) return;

    float4 v = reinterpret_cast<const float4*>(mu + warp * KDIM)[lane];
    __nv_bfloat162 p0 = __floats2bfloat162_rn(v.x, v.y);
    __nv_bfloat162 p1 = __floats2bfloat162_rn(v.z, v.w);
    reinterpret_cast<__nv_bfloat162*>(g_mu_bf + warp * KDIM)[lane * 2 + 0] = p0;
    reinterpret_cast<__nv_bfloat162*>(g_mu_bf + warp * KDIM)[lane * 2 + 1] = p1;

    float a0 = __bfloat162float(p0.x), a1 = __bfloat162float(p0.y);
    float a2 = __bfloat162float(p1.x), a3 = __bfloat162float(p1.y);
    float s = a0 * a0 + a1 * a1 + a2 * a2 + a3 * a3;
    #pragma unroll
    for (int o = 16; o > 0; o >>= 1) s += __shfl_down_sync(0xffffffffu, s, o);
    if (lane == 0) g_m2[warp] = s;
}

// ---------------- persistent main kernel ----------------
__global__ void __launch_bounds__(NTHREADS, 1) km_main(
    const float* __restrict__ z, float* __restrict__ out, int L, int ntiles)
{
    extern __shared__ char smem[];
    const uint32_t sbase = smem_u32(smem);
    float* m2s = reinterpret_cast<float*>(smem + SM_M2);
    float* z2s = reinterpret_cast<float*>(smem + SM_Z2);
    float* mh  = reinterpret_cast<float*>(smem + SM_MH);    // [row][quarter]
    float* red = reinterpret_cast<float*>(smem + SM_RED);
    volatile int* s_tile = reinterpret_cast<volatile int*>(smem + SM_TILE);

    const int tid  = threadIdx.x;
    const int wid  = tid >> 5;
    const int lane = tid & 31;
    const int tg   = lane & 3;          // col pair within n8
    const int g    = lane >> 2;         // row within m16 half
    const int rw   = wid & 3;           // row-group (m32)
    const int nh   = wid >> 2;          // centroid quarter (0..3)
    const int r0   = rw * 32;
    const int nbase = nh * NQ;

    // ---- resident mu tile: 512 x 128 bf16 into padded SMEM rows ----
    for (int idx = tid; idx < CDIM * 16; idx += NTHREADS) {      // 16B chunks
        int c = idx >> 4, kc = idx & 15;
        uint4 q = reinterpret_cast<const uint4*>(g_mu_bf)[idx];
        *reinterpret_cast<uint4*>(smem + SM_MU + c * STRIDE_B + kc * 16) = q;
    }
    for (int i = tid; i < CDIM; i += NTHREADS) m2s[i] = g_m2[i];

    // B ldsm_x4 lane base: lanes 0-7: rows n0..n0+7 k-lo; 8-15: k-hi;
    // 16-23: rows n0+8..n0+15 k-lo; 24-31: k-hi.
    const uint32_t bb = sbase + SM_MU
                      + (lane & 7) * STRIDE_B
                      + (((lane >> 3) & 1) ? 16u : 0u)
                      + (lane >> 4) * 8 * STRIDE_B
                      + nbase * STRIDE_B;
    // A ldsm_x4 lane base (m16 group): lanes 0-15 rows, 16-31 k-hi 16B
    const uint32_t ab = sbase + SM_Z
                      + (lane & 15) * STRIDE_B
                      + ((lane & 16) ? 16u : 0u)
                      + r0 * STRIDE_B;

    while (true) {
        if (tid == 0) *s_tile = (int)atomicAdd(&g_tile, 1u);
        __syncthreads();
        const int tile = *s_tile;
        if (tile >= ntiles) break;
        const size_t m0 = (size_t)tile * MT;

        // ---- load z tile fp32 -> bf16 into padded SMEM ----
        for (int idx = tid; idx < MT * 16; idx += NTHREADS) {
            int row = idx >> 4, kc = idx & 15;
            const float4* p = reinterpret_cast<const float4*>(z + (m0 + row) * KDIM + kc * 8);
            float4 v0 = p[0], v1 = p[1];
            __nv_bfloat162 b0 = __floats2bfloat162_rn(v0.x, v0.y);
            __nv_bfloat162 b1 = __floats2bfloat162_rn(v0.z, v0.w);
            __nv_bfloat162 b2 = __floats2bfloat162_rn(v1.x, v1.y);
            __nv_bfloat162 b3 = __floats2bfloat162_rn(v1.z, v1.w);
            uint4 q;
            q.x = *reinterpret_cast<uint32_t*>(&b0);
            q.y = *reinterpret_cast<uint32_t*>(&b1);
            q.z = *reinterpret_cast<uint32_t*>(&b2);
            q.w = *reinterpret_cast<uint32_t*>(&b3);
            *reinterpret_cast<uint4*>(smem + SM_Z + row * STRIDE_B + kc * 16) = q;
        }
        __syncthreads();

        // ---- |z|^2 per row from the same bf16 values ----
        if (tid < MT) {
            float s = 0.0f;
            #pragma unroll
            for (int j = 0; j < 16; j++) {
                uint4 q = *reinterpret_cast<const uint4*>(smem + SM_Z + tid * STRIDE_B + j * 16);
                uint32_t u[4] = {q.x, q.y, q.z, q.w};
                #pragma unroll
                for (int e = 0; e < 4; e++) {
                    float lo = __uint_as_float(u[e] << 16);
                    float hi = __uint_as_float(u[e] & 0xffff0000u);
                    s = fmaf(lo, lo, s);
                    s = fmaf(hi, hi, s);
                }
            }
            z2s[tid] = s;
        }

        // ---- A fragments: m32 x K128 register-resident (2 groups x 8 k-steps) ----
        uint32_t A[2][8][4];
        #pragma unroll
        for (int rg = 0; rg < 2; rg++)
            #pragma unroll
            for (int kk = 0; kk < 8; kk++)
                ldsm_x4(A[rg][kk][0], A[rg][kk][1], A[rg][kk][2], A[rg][kk][3],
                        ab + rg * 16 * STRIDE_B + kk * 32);

        // ---- 128 centroids per warp: 8 iters of n16, 4 indep chains each ----
        float mn[4] = {INFINITY, INFINITY, INFINITY, INFINITY};   // rows g, g+8, g+16, g+24
        #pragma unroll 1
        for (int nt = 0; nt < NQ / 16; nt++) {
            float acc[2][2][4] = {};
            const uint32_t ba = bb + nt * 16 * STRIDE_B;
            #pragma unroll
            for (int kk = 0; kk < 8; kk++) {
                uint32_t b0, b1, b2, b3;
                ldsm_x4(b0, b1, b2, b3, ba + kk * 32);
                mma_bf16(acc[0][0], A[0][kk], b0, b1);
                mma_bf16(acc[0][1], A[0][kk], b2, b3);
                mma_bf16(acc[1][0], A[1][kk], b0, b1);
                mma_bf16(acc[1][1], A[1][kk], b2, b3);
            }
            const int n0 = nbase + nt * 16;
            #pragma unroll
            for (int c = 0; c < 2; c++) {
                float2 m = *reinterpret_cast<const float2*>(&m2s[n0 + 8 * c + 2 * tg]);
                #pragma unroll
                for (int rg = 0; rg < 2; rg++) {
                    mn[rg * 2 + 0] = fminf(mn[rg * 2 + 0], fmaf(-2.0f, acc[rg][c][0], m.x));
                    mn[rg * 2 + 0] = fminf(mn[rg * 2 + 0], fmaf(-2.0f, acc[rg][c][1], m.y));
                    mn[rg * 2 + 1] = fminf(mn[rg * 2 + 1], fmaf(-2.0f, acc[rg][c][2], m.x));
                    mn[rg * 2 + 1] = fminf(mn[rg * 2 + 1], fmaf(-2.0f, acc[rg][c][3], m.y));
                }
            }
        }

        // ---- min across the 4 threads sharing each row ----
        #pragma unroll
        for (int i = 0; i < 4; i++) {
            mn[i] = fminf(mn[i], __shfl_xor_sync(0xffffffffu, mn[i], 1));
            mn[i] = fminf(mn[i], __shfl_xor_sync(0xffffffffu, mn[i], 2));
        }
        if (tg == 0) {
            mh[(r0 + g)      * 4 + nh] = mn[0];
            mh[(r0 + g + 8)  * 4 + nh] = mn[1];
            mh[(r0 + g + 16) * 4 + nh] = mn[2];
            mh[(r0 + g + 24) * 4 + nh] = mn[3];
        }
        __syncthreads();

        // ---- combine quarters, sqrt, block sum ----
        float s = 0.0f;
        if (tid < MT) {
            float4 q = *reinterpret_cast<const float4*>(&mh[tid * 4]);
            float m = fminf(fminf(q.x, q.y), fminf(q.z, q.w));
            s = sqrtf(fmaxf(z2s[tid] + m, 0.0f));
        }
        #pragma unroll
        for (int o = 16; o > 0; o >>= 1) s += __shfl_down_sync(0xffffffffu, s, o);
        if (tid < MT && lane == 0) red[wid] = s;
        __syncthreads();

        if (tid == 0) {
            float t = red[0] + red[1] + red[2] + red[3];
            atomicAdd(&g_sum, t);
            __threadfence();
            unsigned int c = atomicAdd(&g_cnt, 1u);
            if (c == (unsigned int)(ntiles - 1)) {
                out[0] = (*(volatile float*)&g_sum) / (float)L;
            }
        }
        __syncthreads();   // smem safe to reuse
    }
}

extern "C" void kernel_launch(void* const* d_in, const int* in_sizes, int n_in,
                              void* d_out, int out_size) {
    const float* z  = (const float*)d_in[0];
    const float* mu = (const float*)d_in[1];
    float* out = (float*)d_out;

    int L = in_sizes[0] / KDIM;   // 65536
    int ntiles = L / MT;          // 512

    static int nsm = 0;
    if (nsm == 0) {
        cudaDeviceGetAttribute(&nsm, cudaDevAttrMultiProcessorCount, 0);
        cudaFuncSetAttribute(km_main, cudaFuncAttributeMaxDynamicSharedMemorySize, SMEM_BYTES);
    }
    int grid = (ntiles < nsm) ? ntiles : nsm;

    km_prep<<<64, 256>>>(mu);
    km_main<<<grid, NTHREADS, SMEM_BYTES>>>(z, out, L, ntiles);
}

// round 6
// speedup vs baseline: 1.1336x; 1.1023x over previous
#include <cuda_runtime.h>
#include <cuda_bf16.h>
#include <cstdint>
#include <math.h>

// KMeansClusteringLoss via warp-specialized bf16 HMMA pipeline.
//   cost(l,c) = |mu_c|^2 - 2 <z_l, mu_c>,  d(l) = sqrt(max(|z_l|^2 + min_c cost, 0))
//   out = mean_l d(l)
//
// R6: 8 consumer warps (m32 x n256 HMMA core, as R5) + 8 producer warps that
// prefetch/convert the next z tile into a double-buffered bf16 smem tile.
// Named-barrier full/empty handshake; dynamic tile stealing by producers.

#define KDIM  128
#define CDIM  512
#define MT    128          // z rows per tile
#define NTHREADS 512       // warps 0-7 consumers, 8-15 producers
#define NQ    256          // centroids per consumer warp (2 halves)

#define STRIDE_B 272       // 128 bf16 (256B) + 16B pad -> conflict-free LDSM

// dynamic smem layout (bytes)
#define SM_MU    0                          // 512 x 272 = 139264
#define SM_Z0    139264                     // 128 x 272 = 34816
#define SM_Z1    174080                     // 128 x 272 = 34816
#define SM_M2    208896                     // 512 f32
#define SM_Z2_0  210944                     // 128 f32
#define SM_Z2_1  211456                     // 128 f32
#define SM_MH    211968                     // 128 x 2 f32
#define SM_RED   212992                     // 8 f32
#define SM_PT    213024                     // 2 ints (tile ids)
#define SMEM_BYTES 213056

__device__ float g_sum;
__device__ unsigned int g_cnt;
__device__ unsigned int g_tile;
__device__ __align__(16) __nv_bfloat16 g_mu_bf[CDIM * KDIM];
__device__ float g_m2[CDIM];

// ---------------- helpers ----------------
__device__ __forceinline__ uint32_t smem_u32(const void* p) {
    uint32_t a;
    asm("{ .reg .u64 t; cvta.to.shared.u64 t, %1; cvt.u32.u64 %0, t; }" : "=r"(a) : "l"(p));
    return a;
}
__device__ __forceinline__ void ldsm_x4(uint32_t& r0, uint32_t& r1, uint32_t& r2, uint32_t& r3,
                                        uint32_t addr) {
    asm volatile("ldmatrix.sync.aligned.m8n8.x4.shared.b16 {%0,%1,%2,%3}, [%4];"
                 : "=r"(r0), "=r"(r1), "=r"(r2), "=r"(r3) : "r"(addr));
}
__device__ __forceinline__ void mma_bf16(float* d, const uint32_t* a,
                                         uint32_t b0, uint32_t b1) {
    asm volatile(
        "mma.sync.aligned.m16n8k16.row.col.f32.bf16.bf16.f32 "
        "{%0,%1,%2,%3}, {%4,%5,%6,%7}, {%8,%9}, {%0,%1,%2,%3};"
        : "+f"(d[0]), "+f"(d[1]), "+f"(d[2]), "+f"(d[3])
        : "r"(a[0]), "r"(a[1]), "r"(a[2]), "r"(a[3]), "r"(b0), "r"(b1));
}
#define BAR_SYNC(id, cnt)   asm volatile("bar.sync %0, %1;"   :: "r"(id), "r"(cnt) : "memory")
#define BAR_ARRIVE(id, cnt) asm volatile("bar.arrive %0, %1;" :: "r"(id), "r"(cnt) : "memory")

// Fill a z tile: global fp32 -> bf16 packed smem + per-row |z|^2 (from the
// SAME bf16 values). nthr threads, t = index within group (t&31 == lane&31).
__device__ __forceinline__ void fill_z(const float* __restrict__ z, int tile,
                                       char* smem, int zoff, float* z2buf,
                                       int t, int nthr) {
    const size_t m0 = (size_t)tile * MT;
    const int iters = (MT * 16) / nthr;    // chunks of 8 floats
    #pragma unroll
    for (int it = 0; it < iters; it++) {
        int idx = t + it * nthr;
        int row = idx >> 4, kc = idx & 15;
        const float4* p = reinterpret_cast<const float4*>(z + (m0 + row) * KDIM + kc * 8);
        float4 v0 = p[0], v1 = p[1];
        __nv_bfloat162 b0 = __floats2bfloat162_rn(v0.x, v0.y);
        __nv_bfloat162 b1 = __floats2bfloat162_rn(v0.z, v0.w);
        __nv_bfloat162 b2 = __floats2bfloat162_rn(v1.x, v1.y);
        __nv_bfloat162 b3 = __floats2bfloat162_rn(v1.z, v1.w);
        uint4 q;
        q.x = *reinterpret_cast<uint32_t*>(&b0);
        q.y = *reinterpret_cast<uint32_t*>(&b1);
        q.z = *reinterpret_cast<uint32_t*>(&b2);
        q.w = *reinterpret_cast<uint32_t*>(&b3);
        *reinterpret_cast<uint4*>(smem + zoff + row * STRIDE_B + kc * 16) = q;

        // partial |z|^2 from the converted values
        float s = 0.0f;
        uint32_t u[4] = {q.x, q.y, q.z, q.w};
        #pragma unroll
        for (int e = 0; e < 4; e++) {
            float lo = __uint_as_float(u[e] << 16);
            float hi = __uint_as_float(u[e] & 0xffff0000u);
            s = fmaf(lo, lo, s);
            s = fmaf(hi, hi, s);
        }
        // 16 lanes (kc = lane&15) share one row -> reduce within the 16-lane group
        s += __shfl_xor_sync(0xffffffffu, s, 1);
        s += __shfl_xor_sync(0xffffffffu, s, 2);
        s += __shfl_xor_sync(0xffffffffu, s, 4);
        s += __shfl_xor_sync(0xffffffffu, s, 8);
        if ((t & 15) == 0) z2buf[row] = s;
    }
}

// ---------------- prologue: mu fp32 -> bf16, m2, zero accumulators ----------------
__global__ void km_prep(const float* __restrict__ mu) {
    if (blockIdx.x == 0 && threadIdx.x == 0) { g_sum = 0.0f; g_cnt = 0u; g_tile = 0u; }
    int warp = (blockIdx.x * blockDim.x + threadIdx.x) >> 5;
    int lane = threadIdx.x & 31;
    if (warp >= CDIM) return;

    float4 v = reinterpret_cast<const float4*>(mu + warp * KDIM)[lane];
    __nv_bfloat162 p0 = __floats2bfloat162_rn(v.x, v.y);
    __nv_bfloat162 p1 = __floats2bfloat162_rn(v.z, v.w);
    reinterpret_cast<__nv_bfloat162*>(g_mu_bf + warp * KDIM)[lane * 2 + 0] = p0;
    reinterpret_cast<__nv_bfloat162*>(g_mu_bf + warp * KDIM)[lane * 2 + 1] = p1;

    float a0 = __bfloat162float(p0.x), a1 = __bfloat162float(p0.y);
    float a2 = __bfloat162float(p1.x), a3 = __bfloat162float(p1.y);
    float s = a0 * a0 + a1 * a1 + a2 * a2 + a3 * a3;
    #pragma unroll
    for (int o = 16; o > 0; o >>= 1) s += __shfl_down_sync(0xffffffffu, s, o);
    if (lane == 0) g_m2[warp] = s;
}

// ---------------- persistent warp-specialized kernel ----------------
__global__ void __launch_bounds__(NTHREADS, 1) km_main(
    const float* __restrict__ z, float* __restrict__ out, int L, int ntiles)
{
    extern __shared__ char smem[];
    const uint32_t sbase = smem_u32(smem);
    float* m2s  = reinterpret_cast<float*>(smem + SM_M2);
    float* z2b[2] = { reinterpret_cast<float*>(smem + SM_Z2_0),
                      reinterpret_cast<float*>(smem + SM_Z2_1) };
    float* mh   = reinterpret_cast<float*>(smem + SM_MH);
    float* red  = reinterpret_cast<float*>(smem + SM_RED);
    int* ptile  = reinterpret_cast<int*>(smem + SM_PT);

    const int tid  = threadIdx.x;
    const int wid  = tid >> 5;
    const int lane = tid & 31;

    // ---- prologue (all threads): steal first tile, load mu + m2, fill buf0 ----
    if (tid == 0) ptile[0] = (int)atomicAdd(&g_tile, 1u);   // grid <= ntiles, always valid

    #pragma unroll 4
    for (int idx = tid; idx < CDIM * 17; idx += NTHREADS) {  // 16B chunks, 17/row
        int c = idx / 17, kc = idx % 17;
        if (kc < 16) {
            uint4 q = reinterpret_cast<const uint4*>(g_mu_bf)[c * 16 + kc];
            *reinterpret_cast<uint4*>(smem + SM_MU + c * STRIDE_B + kc * 16) = q;
        }
    }
    for (int i = tid; i < CDIM; i += NTHREADS) m2s[i] = g_m2[i];
    __syncthreads();

    fill_z(z, ptile[0], smem, SM_Z0, z2b[0], tid, NTHREADS);
    __syncthreads();

    if (wid >= 8) {
        // ================= PRODUCER (warps 8-15) =================
        const int ptid = tid - 256;
        for (int i = 1;; i++) {
            const int p = i & 1;
            if (i >= 2) BAR_SYNC(3 + p, 512);                 // wait buffer empty
            if (ptid == 0) {
                int t = (int)atomicAdd(&g_tile, 1u);
                ptile[p] = (t < ntiles) ? t : -1;
            }
            BAR_SYNC(6, 256);                                  // producers: ptile visible
            const int t = ptile[p];
            if (t >= 0)
                fill_z(z, t, smem, p ? SM_Z1 : SM_Z0, z2b[p], ptid, 256);
            __threadfence_block();
            BAR_ARRIVE(1 + p, 512);                            // signal full
            if (t < 0) break;
        }
    } else {
        // ================= CONSUMER (warps 0-7) =================
        const int tg   = lane & 3;          // col pair within n8
        const int g    = lane >> 2;         // row within m16 half
        const int rw   = wid & 3;           // row-group (m32)
        const int nh   = wid >> 2;          // centroid half (0/1)
        const int r0   = rw * 32;
        const int nbase = nh * NQ;

        const uint32_t bb = sbase + SM_MU
                          + (lane & 7) * STRIDE_B
                          + (((lane >> 3) & 1) ? 16u : 0u)
                          + (lane >> 4) * 8 * STRIDE_B
                          + nbase * STRIDE_B;

        for (int i = 0;; i++) {
            const int p = i & 1;
            if (i >= 1) BAR_SYNC(1 + p, 512);                  // wait buffer full
            const int t = ptile[p];
            if (t < 0) break;
            const uint32_t zb = sbase + (p ? SM_Z1 : SM_Z0);

            // ---- A fragments: m32 x K128 register-resident ----
            uint32_t A[2][8][4];
            {
                const uint32_t ab = zb + (lane & 15) * STRIDE_B
                                  + ((lane & 16) ? 16u : 0u) + r0 * STRIDE_B;
                #pragma unroll
                for (int rg = 0; rg < 2; rg++)
                    #pragma unroll
                    for (int kk = 0; kk < 8; kk++)
                        ldsm_x4(A[rg][kk][0], A[rg][kk][1], A[rg][kk][2], A[rg][kk][3],
                                ab + rg * 16 * STRIDE_B + kk * 32);
            }

            // ---- 256 centroids: 16 iters of n16, 4 indep chains each ----
            float mn[4] = {INFINITY, INFINITY, INFINITY, INFINITY};
            #pragma unroll 1
            for (int nt = 0; nt < NQ / 16; nt++) {
                float acc[2][2][4] = {};
                const uint32_t ba = bb + nt * 16 * STRIDE_B;
                #pragma unroll
                for (int kk = 0; kk < 8; kk++) {
                    uint32_t b0, b1, b2, b3;
                    ldsm_x4(b0, b1, b2, b3, ba + kk * 32);
                    mma_bf16(acc[0][0], A[0][kk], b0, b1);
                    mma_bf16(acc[0][1], A[0][kk], b2, b3);
                    mma_bf16(acc[1][0], A[1][kk], b0, b1);
                    mma_bf16(acc[1][1], A[1][kk], b2, b3);
                }
                const int n0 = nbase + nt * 16;
                #pragma unroll
                for (int c = 0; c < 2; c++) {
                    float2 m = *reinterpret_cast<const float2*>(&m2s[n0 + 8 * c + 2 * tg]);
                    #pragma unroll
                    for (int rg = 0; rg < 2; rg++) {
                        mn[rg * 2 + 0] = fminf(mn[rg * 2 + 0], fmaf(-2.0f, acc[rg][c][0], m.x));
                        mn[rg * 2 + 0] = fminf(mn[rg * 2 + 0], fmaf(-2.0f, acc[rg][c][1], m.y));
                        mn[rg * 2 + 1] = fminf(mn[rg * 2 + 1], fmaf(-2.0f, acc[rg][c][2], m.x));
                        mn[rg * 2 + 1] = fminf(mn[rg * 2 + 1], fmaf(-2.0f, acc[rg][c][3], m.y));
                    }
                }
            }

            // ---- min across the 4 threads sharing each row ----
            #pragma unroll
            for (int q = 0; q < 4; q++) {
                mn[q] = fminf(mn[q], __shfl_xor_sync(0xffffffffu, mn[q], 1));
                mn[q] = fminf(mn[q], __shfl_xor_sync(0xffffffffu, mn[q], 2));
            }
            if (tg == 0) {
                mh[(r0 + g)      * 2 + nh] = mn[0];
                mh[(r0 + g + 8)  * 2 + nh] = mn[1];
                mh[(r0 + g + 16) * 2 + nh] = mn[2];
                mh[(r0 + g + 24) * 2 + nh] = mn[3];
            }
            BAR_SYNC(5, 256);                                  // consumers only

            float s = 0.0f;
            if (tid < MT) {
                float m = fminf(mh[tid * 2 + 0], mh[tid * 2 + 1]);
                s = sqrtf(fmaxf(z2b[p][tid] + m, 0.0f));
            }
            #pragma unroll
            for (int o = 16; o > 0; o >>= 1) s += __shfl_down_sync(0xffffffffu, s, o);
            if (lane == 0) red[wid] = s;
            BAR_SYNC(5, 256);

            if (tid == 0) {
                float tt = red[0] + red[1] + red[2] + red[3];
                atomicAdd(&g_sum, tt);
                __threadfence();
                unsigned int c = atomicAdd(&g_cnt, 1u);
                if (c == (unsigned int)(ntiles - 1))
                    out[0] = (*(volatile float*)&g_sum) / (float)L;
            }
            BAR_ARRIVE(3 + p, 512);                            // signal empty
        }
    }
}

extern "C" void kernel_launch(void* const* d_in, const int* in_sizes, int n_in,
                              void* d_out, int out_size) {
    const float* z  = (const float*)d_in[0];
    const float* mu = (const float*)d_in[1];
    float* out = (float*)d_out;

    int L = in_sizes[0] / KDIM;   // 65536
    int ntiles = L / MT;          // 512

    static int nsm = 0;
    if (nsm == 0) {
        cudaDeviceGetAttribute(&nsm, cudaDevAttrMultiProcessorCount, 0);
        cudaFuncSetAttribute(km_main, cudaFuncAttributeMaxDynamicSharedMemorySize, SMEM_BYTES);
    }
    int grid = (ntiles < nsm) ? ntiles : nsm;

    km_prep<<<64, 256>>>(mu);
    km_main<<<grid, NTHREADS, SMEM_BYTES>>>(z, out, L, ntiles);
}